// round 6
// baseline (speedup 1.0000x reference)
#include <cuda_runtime.h>
#include <cuda_bf16.h>

// seg_loss: fused sigmoid-CE + boundary-edge loss + dice — single kernel.
// inputs: c_map float32 [16,4,512,512], gt int32 [16,4,512,512] (binary)
// output: scalar float32
//
// Each block writes 5 float partials to its own slot; the LAST block to finish
// (atomic ticket) reduces all partials from hot L2 and writes the scalar.
// Counter self-resets for graph replay. No init kernel, no second launch.

#define HW_W 512
#define HW_H 512
#define ROWS 16           // rows per block band
#define BANDS 32          // 512 / 16 bands per image
#define NBC 64            // 16 batches * 4 classes
#define NBLK 2048         // NBC * BANDS  (slot = bc*32 + band)
#define TPB 128           // one int4-group per thread across a row

__device__ float g_inter[NBLK];
__device__ float g_ysum[NBLK];
__device__ float g_psum[NBLK];
__device__ float g_ce[NBLK];
__device__ float g_eg[NBLK];
__device__ unsigned int g_ticket = 0;

__device__ __forceinline__ float warp_redf(float v) {
    v += __shfl_down_sync(0xffffffffu, v, 16);
    v += __shfl_down_sync(0xffffffffu, v, 8);
    v += __shfl_down_sync(0xffffffffu, v, 4);
    v += __shfl_down_sync(0xffffffffu, v, 2);
    v += __shfl_down_sync(0xffffffffu, v, 1);
    return v;
}

__global__ __launch_bounds__(TPB)
void seg_fused_kernel(const float* __restrict__ cmap, const int* __restrict__ gt,
                      float* __restrict__ out) {
    const int bc   = blockIdx.x >> 5;          // image (b,c)
    const int band = blockIdx.x & 31;
    const int h0   = band * ROWS;
    const int xg   = threadIdx.x;              // int4-group column 0..127
    const int lane = threadIdx.x & 31;
    const int wid  = threadIdx.x >> 5;

    const size_t img = (size_t)bc * (HW_W * HW_H);
    const size_t colBase = img + (size_t)xg * 4;

    float inter = 0.f, ysum = 0.f, psum = 0.f, ce = 0.f, eg = 0.f;

    // rolling rows: prev (up), cur, nxt (down)
    int4 prev = (h0 > 0) ? *(const int4*)(gt + colBase + (size_t)(h0 - 1) * HW_W)
                         : make_int4(0, 0, 0, 0);
    int4 cur  = *(const int4*)(gt + colBase + (size_t)h0 * HW_W);

    #pragma unroll
    for (int r = 0; r < ROWS; r++) {
        const int h = h0 + r;
        const size_t rowBase = colBase + (size_t)h * HW_W;

        int4 nxt = (h < HW_H - 1) ? *(const int4*)(gt + rowBase + HW_W)
                                  : make_int4(0, 0, 0, 0);
        float4 xv = *(const float4*)(cmap + rowBase);

        // horizontal neighbors of this thread's 4-pixel group
        int lft = __shfl_up_sync(0xffffffffu, cur.w, 1);
        int rgt = __shfl_down_sync(0xffffffffu, cur.x, 1);
        if (lane == 0)  lft = (xg > 0)   ? gt[rowBase - 1] : 0;
        if (lane == 31) rgt = (xg < 127) ? gt[rowBase + 4] : 0;

        int c[4]  = {cur.x, cur.y, cur.z, cur.w};
        int u[4]  = {prev.x, prev.y, prev.z, prev.w};
        int dn[4] = {nxt.x, nxt.y, nxt.z, nxt.w};
        float xs[4] = {xv.x, xv.y, xv.z, xv.w};

        #pragma unroll
        for (int i = 0; i < 4; i++) {
            int l  = (i == 0) ? lft : c[i - 1];
            int rr = (i == 3) ? rgt : c[i + 1];
            int dila = c[i] | u[i] | dn[i] | l | rr;
            int eros = c[i] & u[i] & dn[i] & l & rr;
            int edge = dila & (eros ^ 1);

            float x = xs[i];
            float e   = __expf(-fabsf(x));                   // exp(-|x|)
            float sp  = fmaxf(x, 0.0f) + __logf(1.0f + e);   // softplus(x)
            float inv = __fdividef(1.0f, 1.0f + e);
            float pred = (x >= 0.0f) ? inv : e * inv;        // sigmoid(x)

            float y = (float)c[i];
            ysum  += y;
            psum  += pred;
            inter += y * pred;
            ce    += sp - x * y;
            if (edge) eg += fminf(sp, 100.0f);               // -max(log1p(-pe),-100)
        }

        prev = cur; cur = nxt;
    }

    // block reduction (4 warps)
    inter = warp_redf(inter);
    ysum  = warp_redf(ysum);
    psum  = warp_redf(psum);
    ce    = warp_redf(ce);
    eg    = warp_redf(eg);

    __shared__ float sred[4][5];
    if (lane == 0) {
        sred[wid][0] = inter; sred[wid][1] = ysum; sred[wid][2] = psum;
        sred[wid][3] = ce;    sred[wid][4] = eg;
    }
    __syncthreads();
    if (threadIdx.x == 0) {
        float v0 = 0.f, v1 = 0.f, v2 = 0.f, v3 = 0.f, v4 = 0.f;
        #pragma unroll
        for (int w = 0; w < 4; w++) {
            v0 += sred[w][0]; v1 += sred[w][1]; v2 += sred[w][2];
            v3 += sred[w][3]; v4 += sred[w][4];
        }
        g_inter[blockIdx.x] = v0;
        g_ysum[blockIdx.x]  = v1;
        g_psum[blockIdx.x]  = v2;
        g_ce[blockIdx.x]    = v3;
        g_eg[blockIdx.x]    = v4;
    }

    // ---- last-block final reduction ----
    __shared__ unsigned int s_isLast;
    __threadfence();                       // partials visible before ticket
    __syncthreads();                       // all warps' shared writes done
    if (threadIdx.x == 0) {
        unsigned int rank = atomicAdd(&g_ticket, 1u);
        s_isLast = (rank == NBLK - 1) ? 1u : 0u;
        if (s_isLast) g_ticket = 0;        // reset for next graph replay
    }
    __syncthreads();
    if (!s_isLast) return;

    // Last block: reduce 2048 slots. Slot layout = bc*32 + band, so a warp
    // reading 32 consecutive slots covers exactly one (b,c) -> coalesced.
    const double SMOOTH = 0.0001;
    double dice = 0.0, ced = 0.0, egd = 0.0;

    for (int chunk = wid; chunk < NBC; chunk += 4) {   // chunk == bc
        int s = chunk * BANDS + lane;                  // BANDS==32==warp
        float I = g_inter[s];
        float Y = g_ysum[s];
        float P = g_psum[s];
        float Cf = g_ce[s];
        float Ef = g_eg[s];
        I  = warp_redf(I);
        Y  = warp_redf(Y);
        P  = warp_redf(P);
        Cf = warp_redf(Cf);
        Ef = warp_redf(Ef);
        if (lane == 0) {
            dice += 1.0 - (2.0 * (double)I + SMOOTH)
                        / ((double)Y + (double)P + SMOOTH);
            ced  += (double)Cf;
            egd  += (double)Ef;
        }
    }

    __shared__ double sd[4][3];
    if (lane == 0) { sd[wid][0] = dice; sd[wid][1] = ced; sd[wid][2] = egd; }
    __syncthreads();
    if (threadIdx.x == 0) {
        double D = 0.0, C = 0.0, E = 0.0;
        #pragma unroll
        for (int w = 0; w < 4; w++) { D += sd[w][0]; C += sd[w][1]; E += sd[w][2]; }
        const double N = 16.0 * 4.0 * 512.0 * 512.0;
        out[0] = (float)(C / N + E / N + D / 16.0);
    }
}

extern "C" void kernel_launch(void* const* d_in, const int* in_sizes, int n_in,
                              void* d_out, int out_size) {
    const float* cmap = (const float*)d_in[0];
    const int*   gt   = (const int*)d_in[1];
    float* out = (float*)d_out;

    seg_fused_kernel<<<NBLK, TPB>>>(cmap, gt, out);
}